// round 16
// baseline (speedup 1.0000x reference)
#include <cuda_runtime.h>
#include <math.h>
#include <stdint.h>

#define BATCH 32
#define TSTEPS 12
#define NN 512
#define HH 64
#define EE 10

// ---------------- device state ----------------
__device__ float g_A[NN * NN];
__device__ float g_A2s[NN * NN];
__device__ float g_Ad[BATCH * NN * NN];
__device__ float g_A2d[BATCH * NN * NN];
__device__ float g_h[BATCH * NN * HH];
__device__ float g_zh[BATCH * NN * HH];
__device__ float g_r[BATCH * NN * HH];
__device__ float g_u1m[BATCH * NN * HH];
__device__ float g_u2m[BATCH * NN * HH];
__device__ float g_y1[BATCH * NN * 2];
__device__ float g_y2[BATCH * NN * 2];
__device__ float g_Edyn[BATCH * NN * EE];
__device__ float g_go[BATCH * NN];

__device__ __forceinline__ uint32_t tf32cvt(float x) {
    uint32_t r;
    asm("cvt.rna.tf32.f32 %0, %1;" : "=r"(r) : "f"(x));
    return r;
}

__device__ __forceinline__ void mma_tf32(float* d, uint32_t a0, uint32_t a1, uint32_t a2,
                                         uint32_t a3, uint32_t b0, uint32_t b1) {
    asm volatile(
        "mma.sync.aligned.m16n8k8.row.col.f32.tf32.tf32.f32 "
        "{%0,%1,%2,%3},{%4,%5,%6,%7},{%8,%9},{%0,%1,%2,%3};"
        : "+f"(d[0]), "+f"(d[1]), "+f"(d[2]), "+f"(d[3])
        : "r"(a0), "r"(a1), "r"(a2), "r"(a3), "r"(b0), "r"(b1));
}

__device__ __forceinline__ void cp_async16(uint32_t smem, const void* gmem) {
    asm volatile("cp.async.cg.shared.global [%0], [%1], 16;" :: "r"(smem), "l"(gmem));
}
__device__ __forceinline__ void cp_commit() { asm volatile("cp.async.commit_group;"); }
__device__ __forceinline__ void cp_wait0() { asm volatile("cp.async.wait_group 0;"); }

// ---------------- init ----------------
__global__ void zero_state() {
    int i = blockIdx.x * 256 + threadIdx.x;
    if (i < BATCH * NN * HH) g_h[i] = 0.f;
    if (i < BATCH * NN) g_go[i] = 0.f;
}

// ---------------- graph build: row of softmax(relu(E E^T)), tf32-rounded ----------------
template <bool DYN>
__global__ void graph_build(const float* __restrict__ emb) {
    __shared__ float Es[NN * EE];
    __shared__ float red[8];
    int blk = blockIdx.x;
    int b = DYN ? (blk >> 9) : 0;
    int row = blk & (NN - 1);
    const float* E = DYN ? (g_Edyn + b * NN * EE) : emb;
    int tid = threadIdx.x;
    for (int i = tid; i < NN * EE; i += 256) Es[i] = E[i];
    __syncthreads();
    float er[EE];
#pragma unroll
    for (int j = 0; j < EE; j++) er[j] = Es[row * EE + j];
    float v0 = 0.f, v1 = 0.f;
    int c0 = tid, c1 = tid + 256;
#pragma unroll
    for (int j = 0; j < EE; j++) {
        v0 += er[j] * Es[c0 * EE + j];
        v1 += er[j] * Es[c1 * EE + j];
    }
    v0 = fmaxf(v0, 0.f);
    v1 = fmaxf(v1, 0.f);
    float m = fmaxf(v0, v1);
#pragma unroll
    for (int o = 16; o; o >>= 1) m = fmaxf(m, __shfl_xor_sync(0xffffffffu, m, o));
    if ((tid & 31) == 0) red[tid >> 5] = m;
    __syncthreads();
    m = red[0];
#pragma unroll
    for (int i = 1; i < 8; i++) m = fmaxf(m, red[i]);
    float e0 = expf(v0 - m), e1 = expf(v1 - m);
    float s = e0 + e1;
#pragma unroll
    for (int o = 16; o; o >>= 1) s += __shfl_xor_sync(0xffffffffu, s, o);
    __syncthreads();
    if ((tid & 31) == 0) red[tid >> 5] = s;
    __syncthreads();
    float tot = 0.f;
#pragma unroll
    for (int i = 0; i < 8; i++) tot += red[i];
    float inv = 1.f / tot;
    size_t off = DYN ? ((size_t)b * NN * NN + (size_t)row * NN) : ((size_t)row * NN);
    float* hi = (DYN ? g_Ad : g_A) + off;
    hi[c0] = __uint_as_float(tf32cvt(e0 * inv));
    hi[c1] = __uint_as_float(tf32cvt(e1 * inv));
}

// ---------------- hypernetwork ----------------
__global__ void hyper_kernel(const float* __restrict__ ne,
                             const float* __restrict__ hW,
                             const float* __restrict__ hb) {
    __shared__ float Ws[HH * EE];
    int tid = threadIdx.x;
    for (int i = tid; i < HH * EE; i += 256) Ws[i] = hW[i];
    __syncthreads();
    int lr = tid >> 4, e = tid & 15;
    int row = blockIdx.x * 16 + lr;
    if (e < EE) {
        float acc = hb[e];
        const float* hp = g_h + row * HH;
#pragma unroll
        for (int j = 0; j < HH; j++) acc += hp[j] * Ws[j * EE + e];
        int n = row & (NN - 1);
        g_Edyn[row * EE + e] = ne[n * EE + e] + acc;
    }
}

// ---------------- gemm512s: A2 = tf32(2*(A@A)), single tf32 chain (validated R14/R15) ----------------
#define AS 36
#define XS 72
template <bool DYN>
__global__ void __launch_bounds__(128) gemm512s() {
    __shared__ float sm[2][4608];
    int i0 = blockIdx.x * 64;
    int j0 = blockIdx.y * 64;
    int bz = blockIdx.z;
    size_t boff = (size_t)bz * NN * NN;
    const float* Ahi = (DYN ? g_Ad : g_A) + boff + (size_t)i0 * NN;
    const float* Bhi = (DYN ? g_Ad : g_A) + boff + j0;
    float* Out = (DYN ? g_A2d : g_A2s) + boff;
    int tid = threadIdx.x;

    auto stage = [&](int buf, int k0) {
        float* base = sm[buf];
#pragma unroll
        for (int q = 0; q < 4; q++) {
            int idx = tid + q * 128;
            int r = idx >> 3, c4 = idx & 7;
            cp_async16((uint32_t)__cvta_generic_to_shared(&base[r * AS + c4 * 4]),
                       &Ahi[(size_t)r * NN + k0 + c4 * 4]);
        }
#pragma unroll
        for (int q = 0; q < 4; q++) {
            int idx = tid + q * 128;
            int k = idx >> 4, n4 = idx & 15;
            cp_async16((uint32_t)__cvta_generic_to_shared(&base[2304 + k * XS + n4 * 4]),
                       &Bhi[(size_t)(k0 + k) * NN + n4 * 4]);
        }
        cp_commit();
    };

    stage(0, 0);
    cp_wait0();
    __syncthreads();

    int lane = tid & 31, w = tid >> 5;
    int gid = lane >> 2, tq = lane & 3;
    int R = (w & 1) * 32;
    int CH = (w >> 1) * 32;
    float acc[2][4][4];
#pragma unroll
    for (int rr = 0; rr < 2; rr++)
#pragma unroll
        for (int j = 0; j < 4; j++)
#pragma unroll
            for (int c = 0; c < 4; c++) acc[rr][j][c] = 0.f;

    for (int it = 0; it < 16; it++) {
        int buf = it & 1, nxt = buf ^ 1;
        if (it < 15) stage(nxt, (it + 1) * 32);
        const float* Ah = sm[buf];
        const float* Bh = Ah + 2304;
#pragma unroll
        for (int ks = 0; ks < 4; ks++) {
            int kb = ks * 8;
            uint32_t b0[4], b1[4];
#pragma unroll
            for (int j = 0; j < 4; j++) {
                int nb = CH + j * 8;
                b0[j] = __float_as_uint(Bh[(kb + tq) * XS + nb + gid]);
                b1[j] = __float_as_uint(Bh[(kb + tq + 4) * XS + nb + gid]);
            }
#pragma unroll
            for (int rr = 0; rr < 2; rr++) {
                int Rr = R + rr * 16;
                uint32_t a0 = __float_as_uint(Ah[(Rr + gid) * AS + kb + tq]);
                uint32_t a1 = __float_as_uint(Ah[(Rr + gid + 8) * AS + kb + tq]);
                uint32_t a2 = __float_as_uint(Ah[(Rr + gid) * AS + kb + tq + 4]);
                uint32_t a3 = __float_as_uint(Ah[(Rr + gid + 8) * AS + kb + tq + 4]);
#pragma unroll
                for (int j = 0; j < 4; j++)
                    mma_tf32(acc[rr][j], a0, a1, a2, a3, b0[j], b1[j]);
            }
        }
        if (it < 15) cp_wait0();
        __syncthreads();
    }

#pragma unroll
    for (int rr = 0; rr < 2; rr++) {
#pragma unroll
        for (int j = 0; j < 4; j++) {
            int col = j0 + CH + j * 8 + 2 * tq;
            int row0 = i0 + R + rr * 16 + gid;
            int row1 = row0 + 8;
#pragma unroll
            for (int e = 0; e < 4; e++) {
                int row = (e < 2) ? row0 : row1;
                int cc = col + (e & 1);
                Out[(size_t)row * NN + cc] = __uint_as_float(tf32cvt(2.f * acc[rr][j][e]));
            }
        }
    }
}

// ---------------- conv: u1m = A@X, u2m = 2A^2@X, leads y1/y2 (validated R12/R15, verbatim) ----------------
template <bool BA, int L, int LMODE>
__global__ void __launch_bounds__(128) conv_mma(int xsel, const float* __restrict__ xsrc, int t) {
    __shared__ float As[2][64 * AS];
    __shared__ float Xs[2][32 * XS];
    __shared__ float xsl[L > 0 ? NN * L : 1];
    int b = blockIdx.y;
    int rt = blockIdx.x;
    bool second = rt >= 8;
    int i0 = (second ? rt - 8 : rt) * 64;
    const float* Mbase;
    if (BA) Mbase = (second ? g_A2d : g_Ad) + (size_t)b * NN * NN;
    else    Mbase = second ? g_A2s : g_A;
    Mbase += (size_t)i0 * NN;
    const float* Xb = (xsel ? g_zh : g_h) + b * NN * HH;
    float* Ob = (second ? g_u2m : g_u1m) + b * NN * HH;
    int tid = threadIdx.x;

    if (L > 0) {
        for (int i = tid; i < NN * L; i += 128) {
            int k = i / L, c = i - (i / L) * L;
            float v;
            if (LMODE == 0) v = xsrc[(b * TSTEPS + t) * NN + k];
            else v = (c == 0) ? g_go[b * NN + k] : xsrc[(b * TSTEPS + t) * NN + k];
            xsl[i] = v;
        }
    }

    float4 xr[4];
#pragma unroll
    for (int q = 0; q < 4; q++) {
        int idx = tid + q * 128;
        int r = idx >> 3, c4 = idx & 7;
        cp_async16((uint32_t)__cvta_generic_to_shared(&As[0][r * AS + c4 * 4]),
                   &Mbase[(size_t)r * NN + c4 * 4]);
    }
    cp_commit();
#pragma unroll
    for (int q = 0; q < 4; q++) {
        int idx = tid + q * 128;
        int k = idx >> 4, n4 = idx & 15;
        xr[q] = *(const float4*)&Xb[k * HH + n4 * 4];
    }
#pragma unroll
    for (int q = 0; q < 4; q++) {
        int idx = tid + q * 128;
        int k = idx >> 4, n4 = idx & 15;
        float4 v = xr[q];
        v.x = __uint_as_float(tf32cvt(v.x));
        v.y = __uint_as_float(tf32cvt(v.y));
        v.z = __uint_as_float(tf32cvt(v.z));
        v.w = __uint_as_float(tf32cvt(v.w));
        *(float4*)&Xs[0][k * XS + n4 * 4] = v;
    }
    cp_wait0();
    __syncthreads();

    int lane = tid & 31, w = tid >> 5;
    int gid = lane >> 2, tq = lane & 3;
    int R = (w & 1) * 32;
    int CH = (w >> 1) * 32;
    float acc[2][4][4];
#pragma unroll
    for (int rr = 0; rr < 2; rr++)
#pragma unroll
        for (int j = 0; j < 4; j++)
#pragma unroll
            for (int c = 0; c < 4; c++) acc[rr][j][c] = 0.f;

    int lrow = tid >> 1, lhalf = tid & 1;
    float lacc0 = 0.f, lacc1 = 0.f;

    for (int it = 0; it < 16; it++) {
        int buf = it & 1, nxt = buf ^ 1;
        int k0n = (it + 1) * 32;
        if (it < 15) {
#pragma unroll
            for (int q = 0; q < 4; q++) {
                int idx = tid + q * 128;
                int r = idx >> 3, c4 = idx & 7;
                cp_async16((uint32_t)__cvta_generic_to_shared(&As[nxt][r * AS + c4 * 4]),
                           &Mbase[(size_t)r * NN + k0n + c4 * 4]);
            }
            cp_commit();
#pragma unroll
            for (int q = 0; q < 4; q++) {
                int idx = tid + q * 128;
                int k = idx >> 4, n4 = idx & 15;
                xr[q] = *(const float4*)&Xb[(k0n + k) * HH + n4 * 4];
            }
        }
        const float* Ac = As[buf];
        const float* Xc = Xs[buf];
#pragma unroll
        for (int kss = 0; kss < 4; kss++) {
            int kb = kss * 8;
            uint32_t b0[4], b1[4];
#pragma unroll
            for (int j = 0; j < 4; j++) {
                int nb = CH + j * 8;
                b0[j] = __float_as_uint(Xc[(kb + tq) * XS + nb + gid]);
                b1[j] = __float_as_uint(Xc[(kb + tq + 4) * XS + nb + gid]);
            }
#pragma unroll
            for (int rr = 0; rr < 2; rr++) {
                int Rr = R + rr * 16;
                uint32_t a0 = __float_as_uint(Ac[(Rr + gid) * AS + kb + tq]);
                uint32_t a1 = __float_as_uint(Ac[(Rr + gid + 8) * AS + kb + tq]);
                uint32_t a2 = __float_as_uint(Ac[(Rr + gid) * AS + kb + tq + 4]);
                uint32_t a3 = __float_as_uint(Ac[(Rr + gid + 8) * AS + kb + tq + 4]);
#pragma unroll
                for (int j = 0; j < 4; j++)
                    mma_tf32(acc[rr][j], a0, a1, a2, a3, b0[j], b1[j]);
            }
        }
        if (L > 0) {
            int k0 = it * 32;
#pragma unroll
            for (int j = 0; j < 16; j++) {
                int k = lhalf * 16 + j;
                float a = Ac[lrow * AS + k];
                lacc0 += a * xsl[(k0 + k) * L];
                if (L == 2) lacc1 += a * xsl[(k0 + k) * L + 1];
            }
        }
        if (it < 15) {
#pragma unroll
            for (int q = 0; q < 4; q++) {
                int idx = tid + q * 128;
                int k = idx >> 4, n4 = idx & 15;
                float4 v = xr[q];
                v.x = __uint_as_float(tf32cvt(v.x));
                v.y = __uint_as_float(tf32cvt(v.y));
                v.z = __uint_as_float(tf32cvt(v.z));
                v.w = __uint_as_float(tf32cvt(v.w));
                *(float4*)&Xs[nxt][k * XS + n4 * 4] = v;
            }
            cp_wait0();
        }
        __syncthreads();
    }

    if (L > 0) {
        lacc0 += __shfl_xor_sync(0xffffffffu, lacc0, 1);
        if (L == 2) lacc1 += __shfl_xor_sync(0xffffffffu, lacc1, 1);
        if (lhalf == 0) {
            float* dst = second ? g_y2 : g_y1;
            float sc = second ? 0.5f : 1.f;
            dst[(b * NN + i0 + lrow) * L] = sc * lacc0;
            if (L == 2) dst[(b * NN + i0 + lrow) * L + 1] = sc * lacc1;
        }
    }

#pragma unroll
    for (int rr = 0; rr < 2; rr++) {
#pragma unroll
        for (int j = 0; j < 4; j++) {
            int col = CH + j * 8 + 2 * tq;
            int row0 = i0 + R + rr * 16 + gid;
            int row1 = row0 + 8;
            int o0 = row0 * HH + col;
            int o1 = row1 * HH + col;
            *(float2*)&Ob[o0] = make_float2(acc[rr][j][0], acc[rr][j][1]);
            *(float2*)&Ob[o1] = make_float2(acc[rr][j][2], acc[rr][j][3]);
        }
    }
}

// ---------------- Xs assembly (R12 semantics, 64 rows, 256 threads) ----------------
template <int CIN, bool ENC, bool UPD>
__device__ __forceinline__ void load_xs64(float* Xs, int r0, const float* __restrict__ xsrc, int t) {
    constexpr int K = 3 * CIN;
    constexpr int L = CIN - HH;
    int tid = threadIdx.x;
    for (int i = tid; i < 64 * K; i += 256) {
        int r = i / K, k = i - r * K;
        int seg = k / CIN, c = k - seg * CIN;
        int row = r0 + r, b = row >> 9, n = row & (NN - 1);
        float v;
        if (c < L) {
            float x0;
            if (ENC) x0 = xsrc[(b * TSTEPS + t) * NN + n];
            else x0 = (c == 0) ? g_go[row] : xsrc[(b * TSTEPS + t) * NN + n];
            if (seg == 0) v = x0;
            else if (seg == 1) v = g_y1[row * L + c];
            else v = 2.f * g_y2[row * L + c] - x0;
        } else {
            int cm = c - L;
            float mainv = (UPD ? g_zh : g_h)[row * HH + cm];
            if (seg == 0) v = mainv;
            else if (seg == 1) v = g_u1m[row * HH + cm];
            else v = g_u2m[row * HH + cm] - mainv;
        }
        Xs[i] = v;
    }
}

// ---------------- gate: 64 rows/block, 256 threads; thread = 8 rows x 4 cols ----------------
// dyn smem: Xs 64*K + Ws 32*128
template <int CIN, bool ENC>
__global__ void __launch_bounds__(256) gate_kernel(const float* __restrict__ W,
                                                   const float* __restrict__ bias,
                                                   const float* __restrict__ xsrc, int t) {
    constexpr int K = 3 * CIN;
    extern __shared__ float sm[];
    float* Xs = sm;
    float* Ws = sm + 64 * K;
    int r0 = blockIdx.x * 64;
    int tid = threadIdx.x;
    load_xs64<CIN, ENC, false>(Xs, r0, xsrc, t);
    int j = tid & 31, rg = tid >> 5;   // rg 0..7; all lanes in a warp share rg -> Xs broadcast
    float acc[8][4];
#pragma unroll
    for (int i = 0; i < 8; i++)
#pragma unroll
        for (int c = 0; c < 4; c++) acc[i][c] = 0.f;
    for (int k0 = 0; k0 < K; k0 += 32) {
        int kt = min(32, K - k0);
        __syncthreads();
        for (int l = tid; l < kt * 128; l += 256) Ws[l] = W[k0 * 128 + l];
        __syncthreads();
        for (int kk = 0; kk < kt; kk++) {
            float w0 = Ws[kk * 128 + j];
            float w1 = Ws[kk * 128 + j + 32];
            float w2 = Ws[kk * 128 + j + 64];
            float w3 = Ws[kk * 128 + j + 96];
#pragma unroll
            for (int i = 0; i < 8; i++) {
                float xv = Xs[(rg + 8 * i) * K + k0 + kk];
                acc[i][0] += xv * w0;
                acc[i][1] += xv * w1;
                acc[i][2] += xv * w2;
                acc[i][3] += xv * w3;
            }
        }
    }
    float b0 = bias[j], b1 = bias[j + 32], b2 = bias[j + 64], b3 = bias[j + 96];
#pragma unroll
    for (int i = 0; i < 8; i++) {
        int row = r0 + rg + 8 * i;
        float z0 = 1.f / (1.f + expf(-(acc[i][0] + b0)));
        float z1 = 1.f / (1.f + expf(-(acc[i][1] + b1)));
        float rr0 = 1.f / (1.f + expf(-(acc[i][2] + b2)));
        float rr1 = 1.f / (1.f + expf(-(acc[i][3] + b3)));
        g_zh[row * HH + j] = z0 * g_h[row * HH + j];
        g_zh[row * HH + j + 32] = z1 * g_h[row * HH + j + 32];
        g_r[row * HH + j] = rr0;
        g_r[row * HH + j + 32] = rr1;
    }
}

// ---------------- update: 64 rows/block, 256 threads; thread = 4 rows x 4 cols ----------------
// dyn smem: Xs 64*K + Ws 32*64
template <int CIN, bool DEC>
__global__ void __launch_bounds__(256) upd_kernel(const float* __restrict__ W,
                                                  const float* __restrict__ bias,
                                                  const float* __restrict__ projW,
                                                  const float* __restrict__ projb,
                                                  float* __restrict__ out,
                                                  const float* __restrict__ xsrc, int t) {
    constexpr int K = 3 * CIN;
    extern __shared__ float sm[];
    float* Xs = sm;
    float* Ws = sm + 64 * K;
    int r0 = blockIdx.x * 64;
    int tid = threadIdx.x;
    load_xs64<CIN, !DEC, true>(Xs, r0, xsrc, t);
    int tc = tid & 15, rg = tid >> 4;  // rg 0..15; rows rg + 16*i
    float acc[4][4];
#pragma unroll
    for (int i = 0; i < 4; i++)
#pragma unroll
        for (int c = 0; c < 4; c++) acc[i][c] = 0.f;
    for (int k0 = 0; k0 < K; k0 += 32) {
        int kt = min(32, K - k0);
        __syncthreads();
        for (int l = tid; l < kt * 64; l += 256) Ws[l] = W[k0 * 64 + l];
        __syncthreads();
        for (int kk = 0; kk < kt; kk++) {
            float w0 = Ws[kk * 64 + tc];
            float w1 = Ws[kk * 64 + tc + 16];
            float w2 = Ws[kk * 64 + tc + 32];
            float w3 = Ws[kk * 64 + tc + 48];
#pragma unroll
            for (int i = 0; i < 4; i++) {
                float xv = Xs[(rg + 16 * i) * K + k0 + kk];
                acc[i][0] += xv * w0;
                acc[i][1] += xv * w1;
                acc[i][2] += xv * w2;
                acc[i][3] += xv * w3;
            }
        }
    }
    float bb[4], pw[4];
#pragma unroll
    for (int c = 0; c < 4; c++) {
        bb[c] = bias[tc + 16 * c];
        pw[c] = DEC ? projW[tc + 16 * c] : 0.f;
    }
#pragma unroll
    for (int i = 0; i < 4; i++) {
        int row = r0 + rg + 16 * i;
        float p = 0.f;
#pragma unroll
        for (int c = 0; c < 4; c++) {
            int col = tc + 16 * c;
            float hc = tanhf(acc[i][c] + bb[c]);
            float rr = g_r[row * HH + col];
            float h0 = g_h[row * HH + col];
            float hn = rr * h0 + (1.f - rr) * hc;
            g_h[row * HH + col] = hn;
            if (DEC) p += hn * pw[c];
        }
        if (DEC) {
            p += __shfl_xor_sync(0xffffffffu, p, 8);
            p += __shfl_xor_sync(0xffffffffu, p, 4);
            p += __shfl_xor_sync(0xffffffffu, p, 2);
            p += __shfl_xor_sync(0xffffffffu, p, 1);
            if (tc == 0) {
                float go = p + projb[0];
                g_go[row] = go;
                int b = row >> 9, n = row & (NN - 1);
                out[(b * TSTEPS + t) * NN + n] = go;
            }
        }
    }
}

// ---------------- launch ----------------
extern "C" void kernel_launch(void* const* d_in, const int* in_sizes, int n_in,
                              void* d_out, int out_size) {
    const float* x    = (const float*)d_in[0];
    const float* ycov = (const float*)d_in[1];
    const float* ne   = (const float*)d_in[2];
    const float* egW  = (const float*)d_in[3];
    const float* egb  = (const float*)d_in[4];
    const float* euW  = (const float*)d_in[5];
    const float* eub  = (const float*)d_in[6];
    const float* dgW  = (const float*)d_in[7];
    const float* dgb  = (const float*)d_in[8];
    const float* duW  = (const float*)d_in[9];
    const float* dub  = (const float*)d_in[10];
    const float* pW   = (const float*)d_in[11];
    const float* pb   = (const float*)d_in[12];
    const float* hW   = (const float*)d_in[13];
    const float* hb   = (const float*)d_in[14];
    float* out = (float*)d_out;

    // dynamic smem sizes (bytes)
    const int smemGE = (64 * 195 + 32 * 128) * 4;   // enc gate: 66,368 B
    const int smemGD = (64 * 198 + 32 * 128) * 4;   // dec gate: 67,136 B
    const int smemUE = (64 * 195 + 32 * 64) * 4;    // enc upd:  58,176 B
    const int smemUD = (64 * 198 + 32 * 64) * 4;    // dec upd:  58,944 B
    cudaFuncSetAttribute(gate_kernel<65, true>,  cudaFuncAttributeMaxDynamicSharedMemorySize, smemGE);
    cudaFuncSetAttribute(gate_kernel<66, false>, cudaFuncAttributeMaxDynamicSharedMemorySize, smemGD);
    cudaFuncSetAttribute(upd_kernel<65, false>,  cudaFuncAttributeMaxDynamicSharedMemorySize, smemUE);
    cudaFuncSetAttribute(upd_kernel<66, true>,   cudaFuncAttributeMaxDynamicSharedMemorySize, smemUD);

    zero_state<<<(BATCH * NN * HH + 255) / 256, 256>>>();
    graph_build<false><<<NN, 256>>>(ne);
    gemm512s<false><<<dim3(8, 8, 1), 128>>>();

    dim3 cg(16, BATCH);
    // encoder
    for (int t = 0; t < TSTEPS; t++) {
        conv_mma<false, 1, 0><<<cg, 128>>>(0, x, t);
        gate_kernel<65, true><<<BATCH * NN / 64, 256, smemGE>>>(egW, egb, x, t);
        conv_mma<false, 0, 0><<<cg, 128>>>(1, nullptr, 0);
        upd_kernel<65, false><<<BATCH * NN / 64, 256, smemUE>>>(euW, eub, nullptr, nullptr, nullptr, x, t);
    }
    // dynamic graph + A2d
    hyper_kernel<<<BATCH * NN / 16, 256>>>(ne, hW, hb);
    graph_build<true><<<BATCH * NN, 256>>>(nullptr);
    gemm512s<true><<<dim3(8, 8, BATCH), 128>>>();
    // decoder
    for (int t = 0; t < TSTEPS; t++) {
        conv_mma<true, 2, 1><<<cg, 128>>>(0, ycov, t);
        gate_kernel<66, false><<<BATCH * NN / 64, 256, smemGD>>>(dgW, dgb, ycov, t);
        conv_mma<true, 0, 0><<<cg, 128>>>(1, nullptr, 0);
        upd_kernel<66, true><<<BATCH * NN / 64, 256, smemUD>>>(duW, dub, pW, pb, out, ycov, t);
    }
}

// round 17
// speedup vs baseline: 1.1593x; 1.1593x over previous
#include <cuda_runtime.h>
#include <math.h>
#include <stdint.h>

#define BATCH 32
#define TSTEPS 12
#define NN 512
#define HH 64
#define EE 10

// ---------------- device state ----------------
__device__ float g_A[NN * NN];
__device__ float g_A2s[NN * NN];
__device__ float g_Ad[BATCH * NN * NN];
__device__ float g_A2d[BATCH * NN * NN];
__device__ float g_h[BATCH * NN * HH];
__device__ float g_zh[BATCH * NN * HH];
__device__ float g_r[BATCH * NN * HH];
__device__ float g_u1m[BATCH * NN * HH];
__device__ float g_u2m[BATCH * NN * HH];
__device__ float g_y1[BATCH * NN * 2];
__device__ float g_y2[BATCH * NN * 2];
__device__ float g_Edyn[BATCH * NN * EE];
__device__ float g_go[BATCH * NN];

__device__ __forceinline__ uint32_t tf32cvt(float x) {
    uint32_t r;
    asm("cvt.rna.tf32.f32 %0, %1;" : "=r"(r) : "f"(x));
    return r;
}

__device__ __forceinline__ void mma_tf32(float* d, uint32_t a0, uint32_t a1, uint32_t a2,
                                         uint32_t a3, uint32_t b0, uint32_t b1) {
    asm volatile(
        "mma.sync.aligned.m16n8k8.row.col.f32.tf32.tf32.f32 "
        "{%0,%1,%2,%3},{%4,%5,%6,%7},{%8,%9},{%0,%1,%2,%3};"
        : "+f"(d[0]), "+f"(d[1]), "+f"(d[2]), "+f"(d[3])
        : "r"(a0), "r"(a1), "r"(a2), "r"(a3), "r"(b0), "r"(b1));
}

__device__ __forceinline__ void cp_async16(uint32_t smem, const void* gmem) {
    asm volatile("cp.async.cg.shared.global [%0], [%1], 16;" :: "r"(smem), "l"(gmem));
}
__device__ __forceinline__ void cp_commit() { asm volatile("cp.async.commit_group;"); }
__device__ __forceinline__ void cp_wait0() { asm volatile("cp.async.wait_group 0;"); }

// ---------------- init ----------------
__global__ void zero_state() {
    int i = blockIdx.x * 256 + threadIdx.x;
    if (i < BATCH * NN * HH) g_h[i] = 0.f;
    if (i < BATCH * NN) g_go[i] = 0.f;
}

// ---------------- graph build: row of softmax(relu(E E^T)), tf32-rounded ----------------
template <bool DYN>
__global__ void graph_build(const float* __restrict__ emb) {
    __shared__ float Es[NN * EE];
    __shared__ float red[8];
    int blk = blockIdx.x;
    int b = DYN ? (blk >> 9) : 0;
    int row = blk & (NN - 1);
    const float* E = DYN ? (g_Edyn + b * NN * EE) : emb;
    int tid = threadIdx.x;
    for (int i = tid; i < NN * EE; i += 256) Es[i] = E[i];
    __syncthreads();
    float er[EE];
#pragma unroll
    for (int j = 0; j < EE; j++) er[j] = Es[row * EE + j];
    float v0 = 0.f, v1 = 0.f;
    int c0 = tid, c1 = tid + 256;
#pragma unroll
    for (int j = 0; j < EE; j++) {
        v0 += er[j] * Es[c0 * EE + j];
        v1 += er[j] * Es[c1 * EE + j];
    }
    v0 = fmaxf(v0, 0.f);
    v1 = fmaxf(v1, 0.f);
    float m = fmaxf(v0, v1);
#pragma unroll
    for (int o = 16; o; o >>= 1) m = fmaxf(m, __shfl_xor_sync(0xffffffffu, m, o));
    if ((tid & 31) == 0) red[tid >> 5] = m;
    __syncthreads();
    m = red[0];
#pragma unroll
    for (int i = 1; i < 8; i++) m = fmaxf(m, red[i]);
    float e0 = expf(v0 - m), e1 = expf(v1 - m);
    float s = e0 + e1;
#pragma unroll
    for (int o = 16; o; o >>= 1) s += __shfl_xor_sync(0xffffffffu, s, o);
    __syncthreads();
    if ((tid & 31) == 0) red[tid >> 5] = s;
    __syncthreads();
    float tot = 0.f;
#pragma unroll
    for (int i = 0; i < 8; i++) tot += red[i];
    float inv = 1.f / tot;
    size_t off = DYN ? ((size_t)b * NN * NN + (size_t)row * NN) : ((size_t)row * NN);
    float* hi = (DYN ? g_Ad : g_A) + off;
    hi[c0] = __uint_as_float(tf32cvt(e0 * inv));
    hi[c1] = __uint_as_float(tf32cvt(e1 * inv));
}

// ---------------- hypernetwork ----------------
__global__ void hyper_kernel(const float* __restrict__ ne,
                             const float* __restrict__ hW,
                             const float* __restrict__ hb) {
    __shared__ float Ws[HH * EE];
    int tid = threadIdx.x;
    for (int i = tid; i < HH * EE; i += 256) Ws[i] = hW[i];
    __syncthreads();
    int lr = tid >> 4, e = tid & 15;
    int row = blockIdx.x * 16 + lr;
    if (e < EE) {
        float acc = hb[e];
        const float* hp = g_h + row * HH;
#pragma unroll
        for (int j = 0; j < HH; j++) acc += hp[j] * Ws[j * EE + e];
        int n = row & (NN - 1);
        g_Edyn[row * EE + e] = ne[n * EE + e] + acc;
    }
}

// ---------------- gemm512s: A2 = tf32(2*(A@A)) (validated R14/R15, verbatim) ----------------
#define AS 36
#define XS 72
template <bool DYN>
__global__ void __launch_bounds__(128) gemm512s() {
    __shared__ float sm[2][4608];
    int i0 = blockIdx.x * 64;
    int j0 = blockIdx.y * 64;
    int bz = blockIdx.z;
    size_t boff = (size_t)bz * NN * NN;
    const float* Ahi = (DYN ? g_Ad : g_A) + boff + (size_t)i0 * NN;
    const float* Bhi = (DYN ? g_Ad : g_A) + boff + j0;
    float* Out = (DYN ? g_A2d : g_A2s) + boff;
    int tid = threadIdx.x;

    auto stage = [&](int buf, int k0) {
        float* base = sm[buf];
#pragma unroll
        for (int q = 0; q < 4; q++) {
            int idx = tid + q * 128;
            int r = idx >> 3, c4 = idx & 7;
            cp_async16((uint32_t)__cvta_generic_to_shared(&base[r * AS + c4 * 4]),
                       &Ahi[(size_t)r * NN + k0 + c4 * 4]);
        }
#pragma unroll
        for (int q = 0; q < 4; q++) {
            int idx = tid + q * 128;
            int k = idx >> 4, n4 = idx & 15;
            cp_async16((uint32_t)__cvta_generic_to_shared(&base[2304 + k * XS + n4 * 4]),
                       &Bhi[(size_t)(k0 + k) * NN + n4 * 4]);
        }
        cp_commit();
    };

    stage(0, 0);
    cp_wait0();
    __syncthreads();

    int lane = tid & 31, w = tid >> 5;
    int gid = lane >> 2, tq = lane & 3;
    int R = (w & 1) * 32;
    int CH = (w >> 1) * 32;
    float acc[2][4][4];
#pragma unroll
    for (int rr = 0; rr < 2; rr++)
#pragma unroll
        for (int j = 0; j < 4; j++)
#pragma unroll
            for (int c = 0; c < 4; c++) acc[rr][j][c] = 0.f;

    for (int it = 0; it < 16; it++) {
        int buf = it & 1, nxt = buf ^ 1;
        if (it < 15) stage(nxt, (it + 1) * 32);
        const float* Ah = sm[buf];
        const float* Bh = Ah + 2304;
#pragma unroll
        for (int ks = 0; ks < 4; ks++) {
            int kb = ks * 8;
            uint32_t b0[4], b1[4];
#pragma unroll
            for (int j = 0; j < 4; j++) {
                int nb = CH + j * 8;
                b0[j] = __float_as_uint(Bh[(kb + tq) * XS + nb + gid]);
                b1[j] = __float_as_uint(Bh[(kb + tq + 4) * XS + nb + gid]);
            }
#pragma unroll
            for (int rr = 0; rr < 2; rr++) {
                int Rr = R + rr * 16;
                uint32_t a0 = __float_as_uint(Ah[(Rr + gid) * AS + kb + tq]);
                uint32_t a1 = __float_as_uint(Ah[(Rr + gid + 8) * AS + kb + tq]);
                uint32_t a2 = __float_as_uint(Ah[(Rr + gid) * AS + kb + tq + 4]);
                uint32_t a3 = __float_as_uint(Ah[(Rr + gid + 8) * AS + kb + tq + 4]);
#pragma unroll
                for (int j = 0; j < 4; j++)
                    mma_tf32(acc[rr][j], a0, a1, a2, a3, b0[j], b1[j]);
            }
        }
        if (it < 15) cp_wait0();
        __syncthreads();
    }

#pragma unroll
    for (int rr = 0; rr < 2; rr++) {
#pragma unroll
        for (int j = 0; j < 4; j++) {
            int col = j0 + CH + j * 8 + 2 * tq;
            int row0 = i0 + R + rr * 16 + gid;
            int row1 = row0 + 8;
#pragma unroll
            for (int e = 0; e < 4; e++) {
                int row = (e < 2) ? row0 : row1;
                int cc = col + (e & 1);
                Out[(size_t)row * NN + cc] = __uint_as_float(tf32cvt(2.f * acc[rr][j][e]));
            }
        }
    }
}

// ---------------- conv: u1m = A@X, u2m = 2A^2@X, leads y1/y2 (validated R12/R15, verbatim) ----------------
template <bool BA, int L, int LMODE>
__global__ void __launch_bounds__(128) conv_mma(int xsel, const float* __restrict__ xsrc, int t) {
    __shared__ float As[2][64 * AS];
    __shared__ float Xs[2][32 * XS];
    __shared__ float xsl[L > 0 ? NN * L : 1];
    int b = blockIdx.y;
    int rt = blockIdx.x;
    bool second = rt >= 8;
    int i0 = (second ? rt - 8 : rt) * 64;
    const float* Mbase;
    if (BA) Mbase = (second ? g_A2d : g_Ad) + (size_t)b * NN * NN;
    else    Mbase = second ? g_A2s : g_A;
    Mbase += (size_t)i0 * NN;
    const float* Xb = (xsel ? g_zh : g_h) + b * NN * HH;
    float* Ob = (second ? g_u2m : g_u1m) + b * NN * HH;
    int tid = threadIdx.x;

    if (L > 0) {
        for (int i = tid; i < NN * L; i += 128) {
            int k = i / L, c = i - (i / L) * L;
            float v;
            if (LMODE == 0) v = xsrc[(b * TSTEPS + t) * NN + k];
            else v = (c == 0) ? g_go[b * NN + k] : xsrc[(b * TSTEPS + t) * NN + k];
            xsl[i] = v;
        }
    }

    float4 xr[4];
#pragma unroll
    for (int q = 0; q < 4; q++) {
        int idx = tid + q * 128;
        int r = idx >> 3, c4 = idx & 7;
        cp_async16((uint32_t)__cvta_generic_to_shared(&As[0][r * AS + c4 * 4]),
                   &Mbase[(size_t)r * NN + c4 * 4]);
    }
    cp_commit();
#pragma unroll
    for (int q = 0; q < 4; q++) {
        int idx = tid + q * 128;
        int k = idx >> 4, n4 = idx & 15;
        xr[q] = *(const float4*)&Xb[k * HH + n4 * 4];
    }
#pragma unroll
    for (int q = 0; q < 4; q++) {
        int idx = tid + q * 128;
        int k = idx >> 4, n4 = idx & 15;
        float4 v = xr[q];
        v.x = __uint_as_float(tf32cvt(v.x));
        v.y = __uint_as_float(tf32cvt(v.y));
        v.z = __uint_as_float(tf32cvt(v.z));
        v.w = __uint_as_float(tf32cvt(v.w));
        *(float4*)&Xs[0][k * XS + n4 * 4] = v;
    }
    cp_wait0();
    __syncthreads();

    int lane = tid & 31, w = tid >> 5;
    int gid = lane >> 2, tq = lane & 3;
    int R = (w & 1) * 32;
    int CH = (w >> 1) * 32;
    float acc[2][4][4];
#pragma unroll
    for (int rr = 0; rr < 2; rr++)
#pragma unroll
        for (int j = 0; j < 4; j++)
#pragma unroll
            for (int c = 0; c < 4; c++) acc[rr][j][c] = 0.f;

    int lrow = tid >> 1, lhalf = tid & 1;
    float lacc0 = 0.f, lacc1 = 0.f;

    for (int it = 0; it < 16; it++) {
        int buf = it & 1, nxt = buf ^ 1;
        int k0n = (it + 1) * 32;
        if (it < 15) {
#pragma unroll
            for (int q = 0; q < 4; q++) {
                int idx = tid + q * 128;
                int r = idx >> 3, c4 = idx & 7;
                cp_async16((uint32_t)__cvta_generic_to_shared(&As[nxt][r * AS + c4 * 4]),
                           &Mbase[(size_t)r * NN + k0n + c4 * 4]);
            }
            cp_commit();
#pragma unroll
            for (int q = 0; q < 4; q++) {
                int idx = tid + q * 128;
                int k = idx >> 4, n4 = idx & 15;
                xr[q] = *(const float4*)&Xb[(k0n + k) * HH + n4 * 4];
            }
        }
        const float* Ac = As[buf];
        const float* Xc = Xs[buf];
#pragma unroll
        for (int kss = 0; kss < 4; kss++) {
            int kb = kss * 8;
            uint32_t b0[4], b1[4];
#pragma unroll
            for (int j = 0; j < 4; j++) {
                int nb = CH + j * 8;
                b0[j] = __float_as_uint(Xc[(kb + tq) * XS + nb + gid]);
                b1[j] = __float_as_uint(Xc[(kb + tq + 4) * XS + nb + gid]);
            }
#pragma unroll
            for (int rr = 0; rr < 2; rr++) {
                int Rr = R + rr * 16;
                uint32_t a0 = __float_as_uint(Ac[(Rr + gid) * AS + kb + tq]);
                uint32_t a1 = __float_as_uint(Ac[(Rr + gid + 8) * AS + kb + tq]);
                uint32_t a2 = __float_as_uint(Ac[(Rr + gid) * AS + kb + tq + 4]);
                uint32_t a3 = __float_as_uint(Ac[(Rr + gid + 8) * AS + kb + tq + 4]);
#pragma unroll
                for (int j = 0; j < 4; j++)
                    mma_tf32(acc[rr][j], a0, a1, a2, a3, b0[j], b1[j]);
            }
        }
        if (L > 0) {
            int k0 = it * 32;
#pragma unroll
            for (int j = 0; j < 16; j++) {
                int k = lhalf * 16 + j;
                float a = Ac[lrow * AS + k];
                lacc0 += a * xsl[(k0 + k) * L];
                if (L == 2) lacc1 += a * xsl[(k0 + k) * L + 1];
            }
        }
        if (it < 15) {
#pragma unroll
            for (int q = 0; q < 4; q++) {
                int idx = tid + q * 128;
                int k = idx >> 4, n4 = idx & 15;
                float4 v = xr[q];
                v.x = __uint_as_float(tf32cvt(v.x));
                v.y = __uint_as_float(tf32cvt(v.y));
                v.z = __uint_as_float(tf32cvt(v.z));
                v.w = __uint_as_float(tf32cvt(v.w));
                *(float4*)&Xs[nxt][k * XS + n4 * 4] = v;
            }
            cp_wait0();
        }
        __syncthreads();
    }

    if (L > 0) {
        lacc0 += __shfl_xor_sync(0xffffffffu, lacc0, 1);
        if (L == 2) lacc1 += __shfl_xor_sync(0xffffffffu, lacc1, 1);
        if (lhalf == 0) {
            float* dst = second ? g_y2 : g_y1;
            float sc = second ? 0.5f : 1.f;
            dst[(b * NN + i0 + lrow) * L] = sc * lacc0;
            if (L == 2) dst[(b * NN + i0 + lrow) * L + 1] = sc * lacc1;
        }
    }

#pragma unroll
    for (int rr = 0; rr < 2; rr++) {
#pragma unroll
        for (int j = 0; j < 4; j++) {
            int col = CH + j * 8 + 2 * tq;
            int row0 = i0 + R + rr * 16 + gid;
            int row1 = row0 + 8;
            int o0 = row0 * HH + col;
            int o1 = row1 * HH + col;
            *(float2*)&Ob[o0] = make_float2(acc[rr][j][0], acc[rr][j][1]);
            *(float2*)&Ob[o1] = make_float2(acc[rr][j][2], acc[rr][j][3]);
        }
    }
}

// ---------------- Xs assembly (R12 semantics; padded row stride KP for float4 reads) ----------------
template <int CIN, bool ENC, bool UPD, int KP>
__device__ __forceinline__ void load_xs(float* Xs, int r0, const float* __restrict__ xsrc, int t) {
    constexpr int K = 3 * CIN;
    constexpr int L = CIN - HH;
    int tid = threadIdx.x;
    for (int i = tid; i < 32 * K; i += 256) {
        int r = i / K, k = i - r * K;
        int seg = k / CIN, c = k - seg * CIN;
        int row = r0 + r, b = row >> 9, n = row & (NN - 1);
        float v;
        if (c < L) {
            float x0;
            if (ENC) x0 = xsrc[(b * TSTEPS + t) * NN + n];
            else x0 = (c == 0) ? g_go[row] : xsrc[(b * TSTEPS + t) * NN + n];
            if (seg == 0) v = x0;
            else if (seg == 1) v = g_y1[row * L + c];
            else v = 2.f * g_y2[row * L + c] - x0;
        } else {
            int cm = c - L;
            float mainv = (UPD ? g_zh : g_h)[row * HH + cm];
            if (seg == 0) v = mainv;
            else if (seg == 1) v = g_u1m[row * HH + cm];
            else v = g_u2m[row * HH + cm] - mainv;
        }
        Xs[r * KP + k] = v;
    }
}

// ---------------- gate: 32 rows/block, 256 threads; thread = 4 rows x 4 cols (R15 geometry) ----------------
// Inner loop vectorized: float4 X loads per 4 kk (identical accumulation order).
template <int CIN, bool ENC>
__global__ void gate_kernel(const float* __restrict__ W, const float* __restrict__ bias,
                            const float* __restrict__ xsrc, int t) {
    constexpr int K = 3 * CIN;
    constexpr int KP = (K + 3) & ~3;
    __shared__ float Xs[32 * KP];
    __shared__ float Ws[32 * 128];
    int r0 = blockIdx.x * 32;
    int tid = threadIdx.x;
    load_xs<CIN, ENC, false, KP>(Xs, r0, xsrc, t);
    int j = tid & 31, rg = tid >> 5;
    float acc[4][4];
#pragma unroll
    for (int i = 0; i < 4; i++)
#pragma unroll
        for (int c = 0; c < 4; c++) acc[i][c] = 0.f;
    for (int k0 = 0; k0 < K; k0 += 32) {
        int kt = min(32, K - k0);
        __syncthreads();
        for (int l = tid; l < kt * 128; l += 256) Ws[l] = W[k0 * 128 + l];
        __syncthreads();
        if (kt == 32) {
#pragma unroll
            for (int kk4 = 0; kk4 < 32; kk4 += 4) {
                float4 xv[4];
#pragma unroll
                for (int i = 0; i < 4; i++)
                    xv[i] = *(const float4*)&Xs[(rg + 8 * i) * KP + k0 + kk4];
#pragma unroll
                for (int q = 0; q < 4; q++) {
                    int kk = kk4 + q;
                    float w0 = Ws[kk * 128 + j];
                    float w1 = Ws[kk * 128 + j + 32];
                    float w2 = Ws[kk * 128 + j + 64];
                    float w3 = Ws[kk * 128 + j + 96];
#pragma unroll
                    for (int i = 0; i < 4; i++) {
                        float x = (q == 0) ? xv[i].x : (q == 1) ? xv[i].y : (q == 2) ? xv[i].z : xv[i].w;
                        acc[i][0] += x * w0;
                        acc[i][1] += x * w1;
                        acc[i][2] += x * w2;
                        acc[i][3] += x * w3;
                    }
                }
            }
        } else {
            for (int kk = 0; kk < kt; kk++) {
                float w0 = Ws[kk * 128 + j];
                float w1 = Ws[kk * 128 + j + 32];
                float w2 = Ws[kk * 128 + j + 64];
                float w3 = Ws[kk * 128 + j + 96];
#pragma unroll
                for (int i = 0; i < 4; i++) {
                    float xv = Xs[(rg + 8 * i) * KP + k0 + kk];
                    acc[i][0] += xv * w0;
                    acc[i][1] += xv * w1;
                    acc[i][2] += xv * w2;
                    acc[i][3] += xv * w3;
                }
            }
        }
    }
    float b0 = bias[j], b1 = bias[j + 32], b2 = bias[j + 64], b3 = bias[j + 96];
#pragma unroll
    for (int i = 0; i < 4; i++) {
        int row = r0 + rg + 8 * i;
        float z0 = 1.f / (1.f + expf(-(acc[i][0] + b0)));
        float z1 = 1.f / (1.f + expf(-(acc[i][1] + b1)));
        float rr0 = 1.f / (1.f + expf(-(acc[i][2] + b2)));
        float rr1 = 1.f / (1.f + expf(-(acc[i][3] + b3)));
        g_zh[row * HH + j] = z0 * g_h[row * HH + j];
        g_zh[row * HH + j + 32] = z1 * g_h[row * HH + j + 32];
        g_r[row * HH + j] = rr0;
        g_r[row * HH + j + 32] = rr1;
    }
}

// ---------------- update: 32 rows/block, 256 threads; thread = 4 rows x 2 cols (R12 geometry) ----------------
// Inner loop vectorized: float4 X loads per 4 kk (identical accumulation order).
template <int CIN, bool DEC>
__global__ void upd_kernel(const float* __restrict__ W, const float* __restrict__ bias,
                           const float* __restrict__ projW, const float* __restrict__ projb,
                           float* __restrict__ out, const float* __restrict__ xsrc, int t) {
    constexpr int K = 3 * CIN;
    constexpr int KP = (K + 3) & ~3;
    __shared__ float Xs[32 * KP];
    __shared__ float Ws[32 * 64];
    int r0 = blockIdx.x * 32;
    int tid = threadIdx.x;
    load_xs<CIN, !DEC, true, KP>(Xs, r0, xsrc, t);
    int j = tid & 31, rg = tid >> 5;
    float acc[4][2];
#pragma unroll
    for (int i = 0; i < 4; i++) { acc[i][0] = 0.f; acc[i][1] = 0.f; }
    for (int k0 = 0; k0 < K; k0 += 32) {
        int kt = min(32, K - k0);
        __syncthreads();
        for (int l = tid; l < kt * 64; l += 256) Ws[l] = W[k0 * 64 + l];
        __syncthreads();
        if (kt == 32) {
#pragma unroll
            for (int kk4 = 0; kk4 < 32; kk4 += 4) {
                float4 xv[4];
#pragma unroll
                for (int i = 0; i < 4; i++)
                    xv[i] = *(const float4*)&Xs[(rg + 8 * i) * KP + k0 + kk4];
#pragma unroll
                for (int q = 0; q < 4; q++) {
                    int kk = kk4 + q;
                    float w0 = Ws[kk * 64 + j];
                    float w1 = Ws[kk * 64 + j + 32];
#pragma unroll
                    for (int i = 0; i < 4; i++) {
                        float x = (q == 0) ? xv[i].x : (q == 1) ? xv[i].y : (q == 2) ? xv[i].z : xv[i].w;
                        acc[i][0] += x * w0;
                        acc[i][1] += x * w1;
                    }
                }
            }
        } else {
            for (int kk = 0; kk < kt; kk++) {
                float w0 = Ws[kk * 64 + j];
                float w1 = Ws[kk * 64 + j + 32];
#pragma unroll
                for (int i = 0; i < 4; i++) {
                    float xv = Xs[(rg + 8 * i) * KP + k0 + kk];
                    acc[i][0] += xv * w0;
                    acc[i][1] += xv * w1;
                }
            }
        }
    }
    float b0 = bias[j], b1 = bias[j + 32];
    float pw0 = DEC ? projW[j] : 0.f;
    float pw1 = DEC ? projW[j + 32] : 0.f;
#pragma unroll
    for (int i = 0; i < 4; i++) {
        int row = r0 + rg + 8 * i;
        float hc0 = tanhf(acc[i][0] + b0);
        float hc1 = tanhf(acc[i][1] + b1);
        float rr0 = g_r[row * HH + j], rr1 = g_r[row * HH + j + 32];
        float h0 = g_h[row * HH + j], h1 = g_h[row * HH + j + 32];
        float hn0 = rr0 * h0 + (1.f - rr0) * hc0;
        float hn1 = rr1 * h1 + (1.f - rr1) * hc1;
        g_h[row * HH + j] = hn0;
        g_h[row * HH + j + 32] = hn1;
        if (DEC) {
            float p = hn0 * pw0 + hn1 * pw1;
#pragma unroll
            for (int o = 16; o; o >>= 1) p += __shfl_xor_sync(0xffffffffu, p, o);
            if (j == 0) {
                float go = p + projb[0];
                g_go[row] = go;
                int b = row >> 9, n = row & (NN - 1);
                out[(b * TSTEPS + t) * NN + n] = go;
            }
        }
    }
}

// ---------------- launch ----------------
extern "C" void kernel_launch(void* const* d_in, const int* in_sizes, int n_in,
                              void* d_out, int out_size) {
    const float* x    = (const float*)d_in[0];
    const float* ycov = (const float*)d_in[1];
    const float* ne   = (const float*)d_in[2];
    const float* egW  = (const float*)d_in[3];
    const float* egb  = (const float*)d_in[4];
    const float* euW  = (const float*)d_in[5];
    const float* eub  = (const float*)d_in[6];
    const float* dgW  = (const float*)d_in[7];
    const float* dgb  = (const float*)d_in[8];
    const float* duW  = (const float*)d_in[9];
    const float* dub  = (const float*)d_in[10];
    const float* pW   = (const float*)d_in[11];
    const float* pb   = (const float*)d_in[12];
    const float* hW   = (const float*)d_in[13];
    const float* hb   = (const float*)d_in[14];
    float* out = (float*)d_out;

    zero_state<<<(BATCH * NN * HH + 255) / 256, 256>>>();
    graph_build<false><<<NN, 256>>>(ne);
    gemm512s<false><<<dim3(8, 8, 1), 128>>>();

    dim3 cg(16, BATCH);
    // encoder
    for (int t = 0; t < TSTEPS; t++) {
        conv_mma<false, 1, 0><<<cg, 128>>>(0, x, t);
        gate_kernel<65, true><<<BATCH * NN / 32, 256>>>(egW, egb, x, t);
        conv_mma<false, 0, 0><<<cg, 128>>>(1, nullptr, 0);
        upd_kernel<65, false><<<BATCH * NN / 32, 256>>>(euW, eub, nullptr, nullptr, nullptr, x, t);
    }
    // dynamic graph + A2d
    hyper_kernel<<<BATCH * NN / 16, 256>>>(ne, hW, hb);
    graph_build<true><<<BATCH * NN, 256>>>(nullptr);
    gemm512s<true><<<dim3(8, 8, BATCH), 128>>>();
    // decoder
    for (int t = 0; t < TSTEPS; t++) {
        conv_mma<true, 2, 1><<<cg, 128>>>(0, ycov, t);
        gate_kernel<66, false><<<BATCH * NN / 32, 256>>>(dgW, dgb, ycov, t);
        conv_mma<true, 0, 0><<<cg, 128>>>(1, nullptr, 0);
        upd_kernel<66, true><<<BATCH * NN / 32, 256>>>(duW, dub, pW, pb, out, ycov, t);
    }
}